// round 1
// baseline (speedup 1.0000x reference)
#include <cuda_runtime.h>

// Problem constants
#define N_   8
#define C_   4
#define H_   64
#define W_   64
#define F_   16
#define KK   5
#define HO   60
#define WO   60
#define NTAPS (KK*KK*C_)     // 100
#define NIN  (N_*C_*H_*W_)   // 131072

// Scratch (device globals; no allocation allowed)
// g_in[i] = { e^x, x e^x, e^-x, -x e^-x } for input element i
__device__ float4 g_in[NIN];
// g_w[tap][type][f], type: 0=e^{k1}, 1=k1 e^{k1}, 2=e^{k2}, 3=k2 e^{k2}
__device__ float g_w[NTAPS*4*F_];

__global__ void prep_x_kernel(const float* __restrict__ x) {
    int i = blockIdx.x * blockDim.x + threadIdx.x;
    if (i < NIN) {
        float v  = x[i];
        float e  = __expf(v);
        float en = __expf(-v);
        g_in[i] = make_float4(e, v * e, en, -v * en);
    }
}

__global__ void prep_w_kernel(const float* __restrict__ k1, const float* __restrict__ k2) {
    int i = blockIdx.x * blockDim.x + threadIdx.x;   // i = tap*F + f  (tap = (kh*5+kw)*C + c)
    if (i < NTAPS * F_) {
        int tap = i / F_;
        int f   = i % F_;
        float v1 = k1[i];
        float v2 = k2[i];
        float e1 = __expf(v1);
        float e2 = __expf(v2);
        g_w[(tap*4 + 0)*F_ + f] = e1;
        g_w[(tap*4 + 1)*F_ + f] = v1 * e1;
        g_w[(tap*4 + 2)*F_ + f] = e2;
        g_w[(tap*4 + 3)*F_ + f] = v2 * e2;
    }
}

// Block: one (n, ho) output row. blockDim = (64, 4): x = wo lane (60 active),
// y = f-group of 4 filters. Warps are uniform in f-group -> weight LDS broadcast.
__global__ __launch_bounds__(256) void smorph_main_kernel(
    const float* __restrict__ bias, float* __restrict__ out)
{
    __shared__ float  sw[NTAPS*4*F_];        // 25600 B
    __shared__ float4 sin_[C_][KK][W_];      // 20480 B

    const int ho  = blockIdx.x;
    const int n   = blockIdx.y;
    const int tid = threadIdx.y * 64 + threadIdx.x;

    // Load weights into smem
    #pragma unroll 4
    for (int i = tid; i < NTAPS*4*F_; i += 256) sw[i] = g_w[i];

    // Load input rows ho..ho+4 for all channels (float4 each)
    const float4* gi = g_in + (size_t)n * C_ * H_ * W_;
    float4* sflat = &sin_[0][0][0];
    #pragma unroll
    for (int i = tid; i < C_*KK*W_; i += 256) {
        int w  = i & (W_ - 1);
        int r  = i >> 6;            // c*KK + dh
        int c  = r / KK;
        int dh = r - c * KK;
        sflat[i] = gi[(c * H_ + ho + dh) * W_ + w];
    }
    __syncthreads();

    const int wo = threadIdx.x;
    const int fg = threadIdx.y;
    if (wo >= WO) return;

    float acc0[4] = {0.f, 0.f, 0.f, 0.f};   // sum a * ek1
    float acc1[4] = {0.f, 0.f, 0.f, 0.f};   // sum a*wk1 + b*ek1
    float acc2[4] = {0.f, 0.f, 0.f, 0.f};   // sum a' * ek2
    float acc3[4] = {0.f, 0.f, 0.f, 0.f};   // sum a'*wk2 + b'*ek2

    // kh outer (not unrolled) keeps body ~20 taps (~10KB SASS) inside I$.
    #pragma unroll 1
    for (int kh = 0; kh < KK; kh++) {
        #pragma unroll
        for (int kw = 0; kw < KK; kw++) {
            #pragma unroll
            for (int c = 0; c < C_; c++) {
                float4 in = sin_[c][kh][wo + kw];
                int tap = (kh * KK + kw) * C_ + c;
                const float* wp = sw + tap * (4 * F_) + fg * 4;
                float4 w0 = *(const float4*)(wp);
                float4 w1 = *(const float4*)(wp + F_);
                float4 w2 = *(const float4*)(wp + 2 * F_);
                float4 w3 = *(const float4*)(wp + 3 * F_);

                acc0[0] = fmaf(in.x, w0.x, acc0[0]);
                acc0[1] = fmaf(in.x, w0.y, acc0[1]);
                acc0[2] = fmaf(in.x, w0.z, acc0[2]);
                acc0[3] = fmaf(in.x, w0.w, acc0[3]);

                acc1[0] = fmaf(in.x, w1.x, fmaf(in.y, w0.x, acc1[0]));
                acc1[1] = fmaf(in.x, w1.y, fmaf(in.y, w0.y, acc1[1]));
                acc1[2] = fmaf(in.x, w1.z, fmaf(in.y, w0.z, acc1[2]));
                acc1[3] = fmaf(in.x, w1.w, fmaf(in.y, w0.w, acc1[3]));

                acc2[0] = fmaf(in.z, w2.x, acc2[0]);
                acc2[1] = fmaf(in.z, w2.y, acc2[1]);
                acc2[2] = fmaf(in.z, w2.z, acc2[2]);
                acc2[3] = fmaf(in.z, w2.w, acc2[3]);

                acc3[0] = fmaf(in.z, w3.x, fmaf(in.w, w2.x, acc3[0]));
                acc3[1] = fmaf(in.z, w3.y, fmaf(in.w, w2.y, acc3[1]));
                acc3[2] = fmaf(in.z, w3.z, fmaf(in.w, w2.z, acc3[2]));
                acc3[3] = fmaf(in.z, w3.w, fmaf(in.w, w2.w, acc3[3]));
            }
        }
    }

    // Epilogue: y = num1/den1 + num2/den2 + bias  (denominators are sums of exps > 0)
    const float4 b4 = *(const float4*)(bias + fg * 4);
    float bj[4] = {b4.x, b4.y, b4.z, b4.w};
    float* op = out + (((size_t)n * F_ + fg * 4) * HO + ho) * WO + wo;
    #pragma unroll
    for (int j = 0; j < 4; j++) {
        float y = __fdividef(acc1[j], acc0[j]) + __fdividef(acc3[j], acc2[j]) + bj[j];
        op[(size_t)j * HO * WO] = y;
    }
}

extern "C" void kernel_launch(void* const* d_in, const int* in_sizes, int n_in,
                              void* d_out, int out_size) {
    const float* x    = (const float*)d_in[0];
    const float* k1   = (const float*)d_in[1];
    const float* k2   = (const float*)d_in[2];
    const float* bias = (const float*)d_in[3];
    float* out = (float*)d_out;

    prep_x_kernel<<<(NIN + 255) / 256, 256>>>(x);
    prep_w_kernel<<<(NTAPS * F_ + 255) / 256, 256>>>(k1, k2);

    dim3 grid(HO, N_);
    dim3 block(64, 4);
    smorph_main_kernel<<<grid, block>>>(bias, out);
}

// round 2
// speedup vs baseline: 1.0685x; 1.0685x over previous
#include <cuda_runtime.h>

#define N_   8
#define C_   4
#define H_   64
#define W_   64
#define F_   16
#define KK   5
#define HO   60
#define WO   60
#define NTAPS (KK*KK*C_)     // 100
#define NIN  (N_*C_*H_*W_)   // 131072

typedef unsigned long long u64;

// Scratch (device globals; no allocation allowed)
__device__ float4 g_in[NIN];           // { e^x, x e^x, e^-x, -x e^-x }
__device__ float  g_w[NTAPS*4*F_];     // [tap][type][f]: 0=e^k1, 1=k1 e^k1, 2=e^k2, 3=k2 e^k2

__device__ __forceinline__ u64 ffma2(u64 a, u64 b, u64 c) {
    u64 d; asm("fma.rn.f32x2 %0, %1, %2, %3;" : "=l"(d) : "l"(a), "l"(b), "l"(c)); return d;
}
__device__ __forceinline__ u64 dup2(float x) {
    u64 d; asm("mov.b64 %0, {%1, %1};" : "=l"(d) : "f"(x)); return d;
}
__device__ __forceinline__ float2 unpk2(u64 v) {
    float2 r; asm("mov.b64 {%0, %1}, %2;" : "=f"(r.x), "=f"(r.y) : "l"(v)); return r;
}

// Fused prep: blocks 0..127 transform x (4 elems/thread, vectorized);
// block 128 transforms the 1600 kernel weights.
__global__ __launch_bounds__(256) void prep_kernel(
    const float* __restrict__ x, const float* __restrict__ k1, const float* __restrict__ k2)
{
    if (blockIdx.x < 128) {
        int i = (blockIdx.x * 256 + threadIdx.x) * 4;     // NIN = 128*256*4 exactly
        float4 v = *(const float4*)(x + i);
        #pragma unroll
        for (int j = 0; j < 4; j++) {
            float xv = (&v.x)[j];
            float e  = __expf(xv);
            float en = __expf(-xv);
            g_in[i + j] = make_float4(e, xv * e, en, -xv * en);
        }
    } else {
        for (int i = threadIdx.x; i < NTAPS * F_; i += 256) {
            int tap = i / F_;
            int f   = i - tap * F_;
            float v1 = k1[i], v2 = k2[i];
            float e1 = __expf(v1), e2 = __expf(v2);
            g_w[(tap*4 + 0)*F_ + f] = e1;
            g_w[(tap*4 + 1)*F_ + f] = v1 * e1;
            g_w[(tap*4 + 2)*F_ + f] = e2;
            g_w[(tap*4 + 3)*F_ + f] = v2 * e2;
        }
    }
}

// Block: one (n, ho) output row. blockDim = (64, 2): x = wo lane (60 active),
// y = fg, each thread computes 8 filters with packed f32x2 accumulators.
__global__ __launch_bounds__(128) void smorph_main_kernel(
    const float* __restrict__ bias, float* __restrict__ out)
{
    __shared__ __align__(16) float  sw[NTAPS*4*F_];   // 25600 B
    __shared__ float4 sin_[C_][KK][W_];               // 20480 B

    const int ho  = blockIdx.x;
    const int n   = blockIdx.y;
    const int tid = threadIdx.y * 64 + threadIdx.x;

    #pragma unroll 8
    for (int i = tid; i < NTAPS*4*F_; i += 128) sw[i] = g_w[i];

    const float4* gi = g_in + (size_t)n * C_ * H_ * W_;
    float4* sflat = &sin_[0][0][0];
    #pragma unroll
    for (int i = tid; i < C_*KK*W_; i += 128) {
        int w  = i & (W_ - 1);
        int r  = i >> 6;            // c*KK + dh
        int c  = r / KK;
        int dh = r - c * KK;
        sflat[i] = gi[(c * H_ + ho + dh) * W_ + w];
    }
    __syncthreads();

    const int wo = threadIdx.x;
    const int fg = threadIdx.y;          // filters fg*8 .. fg*8+7
    if (wo >= WO) return;

    u64 acc0[4] = {0,0,0,0};   // sum a * ek1            (f32x2 pairs)
    u64 acc1[4] = {0,0,0,0};   // sum a*wk1 + b*ek1
    u64 acc2[4] = {0,0,0,0};   // sum a' * ek2
    u64 acc3[4] = {0,0,0,0};   // sum a'*wk2 + b'*ek2

    const u64* swu = (const u64*)sw;     // per tap: 32 u64; type t at +t*8; pair j at +fg*4+j

    #pragma unroll 1
    for (int kh = 0; kh < KK; kh++) {
        #pragma unroll
        for (int kw = 0; kw < KK; kw++) {
            #pragma unroll
            for (int c = 0; c < C_; c++) {
                float4 in = sin_[c][kh][wo + kw];
                u64 ax = dup2(in.x);
                u64 bx = dup2(in.y);
                u64 az = dup2(in.z);
                u64 bw = dup2(in.w);
                int tap = (kh * KK + kw) * C_ + c;
                const u64* wp = swu + tap * 32 + fg * 4;
                #pragma unroll
                for (int j = 0; j < 4; j++) {
                    u64 w0 = wp[j];
                    u64 w1 = wp[8 + j];
                    u64 w2 = wp[16 + j];
                    u64 w3 = wp[24 + j];
                    acc0[j] = ffma2(ax, w0, acc0[j]);
                    acc1[j] = ffma2(ax, w1, ffma2(bx, w0, acc1[j]));
                    acc2[j] = ffma2(az, w2, acc2[j]);
                    acc3[j] = ffma2(az, w3, ffma2(bw, w2, acc3[j]));
                }
            }
        }
    }

    // Epilogue: y = num1/den1 + num2/den2 + bias (denominators strictly > 0)
    float* op = out + (((size_t)n * F_ + fg * 8) * HO + ho) * WO + wo;
    #pragma unroll
    for (int j = 0; j < 4; j++) {
        float2 d1 = unpk2(acc0[j]);
        float2 n1 = unpk2(acc1[j]);
        float2 d2 = unpk2(acc2[j]);
        float2 n2 = unpk2(acc3[j]);
        int f = 2 * j;
        float y0 = __fdividef(n1.x, d1.x) + __fdividef(n2.x, d2.x) + bias[fg*8 + f];
        float y1 = __fdividef(n1.y, d1.y) + __fdividef(n2.y, d2.y) + bias[fg*8 + f + 1];
        op[(size_t)f       * HO * WO] = y0;
        op[(size_t)(f + 1) * HO * WO] = y1;
    }
}

extern "C" void kernel_launch(void* const* d_in, const int* in_sizes, int n_in,
                              void* d_out, int out_size) {
    const float* x    = (const float*)d_in[0];
    const float* k1   = (const float*)d_in[1];
    const float* k2   = (const float*)d_in[2];
    const float* bias = (const float*)d_in[3];
    float* out = (float*)d_out;

    prep_kernel<<<129, 256>>>(x, k1, k2);

    dim3 grid(HO, N_);
    dim3 block(64, 2);
    smorph_main_kernel<<<grid, block>>>(bias, out);
}

// round 3
// speedup vs baseline: 1.1497x; 1.0760x over previous
#include <cuda_runtime.h>

#define N_   8
#define C_   4
#define H_   64
#define W_   64
#define F_   16
#define KK   5
#define HO   60
#define WO   60
#define NTAPS (KK*KK*C_)     // 100

typedef unsigned long long u64;

__device__ __forceinline__ u64 ffma2(u64 a, u64 b, u64 c) {
    u64 d; asm("fma.rn.f32x2 %0, %1, %2, %3;" : "=l"(d) : "l"(a), "l"(b), "l"(c)); return d;
}
__device__ __forceinline__ u64 dup2(float x) {
    u64 d; asm("mov.b64 %0, {%1, %1};" : "=l"(d) : "f"(x)); return d;
}
__device__ __forceinline__ float2 unpk2(u64 v) {
    float2 r; asm("mov.b64 {%0, %1}, %2;" : "=f"(r.x), "=f"(r.y) : "l"(v)); return r;
}

// Single fused kernel. Block = one (n, ho) output row. blockDim (64,2):
// x = wo lane, y = fg (8 filters each), packed f32x2 accumulators.
// Each block transforms the weights (3200 exps) and its own input tile
// (1280 elems * 2 exps) in-block: MUFU cost is trivial, and it removes
// two prep launches plus the 2.5MB global scratch round-trip.
__global__ __launch_bounds__(128, 4) void smorph_fused_kernel(
    const float* __restrict__ x, const float* __restrict__ k1,
    const float* __restrict__ k2, const float* __restrict__ bias,
    float* __restrict__ out)
{
    // sw layout: [tap][fg][ w0[8] w1[8] w2[8] w3[8] ]  -> 128B contiguous per (tap,fg)
    __shared__ __align__(16) float  sw[NTAPS * 64];   // 25600 B
    __shared__ float4 sin_[C_][KK][W_];               // 20480 B

    const int ho  = blockIdx.x;
    const int n   = blockIdx.y;
    const int tid = threadIdx.y * 64 + threadIdx.x;

    // ---- Phase 1: weight transform (k index i = tap*F + f) ----
    #pragma unroll
    for (int i = tid; i < NTAPS * F_; i += 128) {
        int tap = i >> 4;
        int f   = i & 15;
        int fgw = f >> 3;
        int fi  = f & 7;
        float v1 = k1[i], v2 = k2[i];
        float e1 = __expf(v1), e2 = __expf(v2);
        float* p = sw + tap * 64 + fgw * 32 + fi;
        p[0]  = e1;
        p[8]  = v1 * e1;
        p[16] = e2;
        p[24] = v2 * e2;
    }

    // ---- Phase 2: input transform for rows ho..ho+4, all channels ----
    const float* gx = x + (size_t)n * C_ * H_ * W_;
    float4* sflat = &sin_[0][0][0];
    #pragma unroll
    for (int i = tid; i < C_ * KK * W_; i += 128) {
        int w  = i & (W_ - 1);
        int r  = i >> 6;            // c*KK + dh
        int c  = r / KK;
        int dh = r - c * KK;
        float xv = gx[(c * H_ + ho + dh) * W_ + w];
        float e  = __expf(xv);
        float en = __expf(-xv);
        sflat[i] = make_float4(e, xv * e, en, -xv * en);
    }
    __syncthreads();

    const int wo = threadIdx.x;
    const int fg = threadIdx.y;          // filters fg*8 .. fg*8+7
    if (wo >= WO) return;

    u64 acc0[4] = {0,0,0,0};   // sum a * ek1
    u64 acc1[4] = {0,0,0,0};   // sum a*wk1 + b*ek1
    u64 acc2[4] = {0,0,0,0};   // sum a' * ek2
    u64 acc3[4] = {0,0,0,0};   // sum a'*wk2 + b'*ek2

    const float4* swbase = (const float4*)sw + fg * 8;   // 16 float4 per tap

    #pragma unroll 1
    for (int kh = 0; kh < KK; kh++) {
        #pragma unroll
        for (int kw = 0; kw < KK; kw++) {
            #pragma unroll
            for (int c = 0; c < C_; c++) {
                const int tap = (kh * KK + kw) * C_ + c;
                // 8 consecutive LDS.128 (warp-uniform -> broadcast)
                float4 wv[8];
                const float4* wp4 = swbase + tap * 16;
                #pragma unroll
                for (int q = 0; q < 8; q++) wv[q] = wp4[q];
                const u64* wu = (const u64*)wv;   // u[0..3]=w0, u[4..7]=w1, u[8..11]=w2, u[12..15]=w3

                float4 in = sin_[c][kh][wo + kw];
                u64 ax = dup2(in.x);
                u64 bx = dup2(in.y);
                u64 az = dup2(in.z);
                u64 bw = dup2(in.w);

                #pragma unroll
                for (int j = 0; j < 4; j++) {
                    acc0[j] = ffma2(ax, wu[j],      acc0[j]);
                    acc1[j] = ffma2(ax, wu[4 + j],  ffma2(bx, wu[j],     acc1[j]));
                    acc2[j] = ffma2(az, wu[8 + j],  acc2[j]);
                    acc3[j] = ffma2(az, wu[12 + j], ffma2(bw, wu[8 + j], acc3[j]));
                }
            }
        }
    }

    // Epilogue: y = num1/den1 + num2/den2 + bias (denominators strictly > 0)
    float* op = out + (((size_t)n * F_ + fg * 8) * HO + ho) * WO + wo;
    #pragma unroll
    for (int j = 0; j < 4; j++) {
        float2 d1 = unpk2(acc0[j]);
        float2 n1 = unpk2(acc1[j]);
        float2 d2 = unpk2(acc2[j]);
        float2 n2 = unpk2(acc3[j]);
        int f = 2 * j;
        float y0 = __fdividef(n1.x, d1.x) + __fdividef(n2.x, d2.x) + bias[fg*8 + f];
        float y1 = __fdividef(n1.y, d1.y) + __fdividef(n2.y, d2.y) + bias[fg*8 + f + 1];
        op[(size_t)f       * HO * WO] = y0;
        op[(size_t)(f + 1) * HO * WO] = y1;
    }
}

extern "C" void kernel_launch(void* const* d_in, const int* in_sizes, int n_in,
                              void* d_out, int out_size) {
    const float* x    = (const float*)d_in[0];
    const float* k1   = (const float*)d_in[1];
    const float* k2   = (const float*)d_in[2];
    const float* bias = (const float*)d_in[3];
    float* out = (float*)d_out;

    dim3 grid(HO, N_);
    dim3 block(64, 2);
    smorph_fused_kernel<<<grid, block>>>(x, k1, k2, bias, out);
}

// round 5
// speedup vs baseline: 1.1606x; 1.0094x over previous
#include <cuda_runtime.h>

#define N_   8
#define C_   4
#define H_   64
#define W_   64
#define F_   16
#define KK   5
#define HO   60
#define WO   60
#define NTAPS (KK*KK*C_)     // 100

typedef unsigned long long u64;

__device__ __forceinline__ u64 ffma2(u64 a, u64 b, u64 c) {
    u64 d; asm("fma.rn.f32x2 %0, %1, %2, %3;" : "=l"(d) : "l"(a), "l"(b), "l"(c)); return d;
}
__device__ __forceinline__ u64 dup2(float x) {
    u64 d; asm("mov.b64 %0, {%1, %1};" : "=l"(d) : "f"(x)); return d;
}
__device__ __forceinline__ float2 unpk2(u64 v) {
    float2 r; asm("mov.b64 {%0, %1}, %2;" : "=f"(r.x), "=f"(r.y) : "l"(v)); return r;
}

// Single fused kernel. Block = one (n, ho) output row. blockDim (64,4):
// x = wo lane, y = fg (4 filters each as 2 f32x2 pairs).
// 256 threads/block doubles warps/SMSP vs the 8f/thread version; per-thread
// register state is tiny (8 acc u64), so ptxas can pipeline LDS deeply.
__global__ __launch_bounds__(256) void smorph_fused_kernel(
    const float* __restrict__ x, const float* __restrict__ k1,
    const float* __restrict__ k2, const float* __restrict__ bias,
    float* __restrict__ out)
{
    // sw layout per tap (64 floats): [fg][ w0[4] w1[4] w2[4] w3[4] ]
    __shared__ __align__(16) float  sw[NTAPS * 64];   // 25600 B
    __shared__ float4 sin_[C_][KK][W_];               // 20480 B

    const int ho  = blockIdx.x;
    const int n   = blockIdx.y;
    const int tid = threadIdx.y * 64 + threadIdx.x;

    // ---- Phase 1: weight transform (i = tap*16 + f) ----
    #pragma unroll
    for (int i = tid; i < NTAPS * F_; i += 256) {
        int tap = i >> 4;
        int f   = i & 15;
        int fgw = f >> 2;
        int fi  = f & 3;
        float v1 = k1[i], v2 = k2[i];
        float e1 = __expf(v1), e2 = __expf(v2);
        float* p = sw + tap * 64 + fgw * 16 + fi;
        p[0]  = e1;
        p[4]  = v1 * e1;
        p[8]  = e2;
        p[12] = v2 * e2;
    }

    // ---- Phase 2: input transform for rows ho..ho+4, all channels ----
    const float* gx = x + (size_t)n * C_ * H_ * W_;
    float4* sflat = &sin_[0][0][0];
    #pragma unroll
    for (int i = tid; i < C_ * KK * W_; i += 256) {
        int w  = i & (W_ - 1);
        int r  = i >> 6;            // c*KK + dh
        int c  = r / KK;
        int dh = r - c * KK;
        float xv = gx[(c * H_ + ho + dh) * W_ + w];
        float e  = __expf(xv);
        float en = __expf(-xv);
        sflat[i] = make_float4(e, xv * e, en, -xv * en);
    }
    __syncthreads();

    const int wo = threadIdx.x;
    const int fg = threadIdx.y;          // filters fg*4 .. fg*4+3
    if (wo >= WO) return;

    u64 acc0[2] = {0,0};   // sum a * ek1
    u64 acc1[2] = {0,0};   // sum a*wk1 + b*ek1
    u64 acc2[2] = {0,0};   // sum a' * ek2
    u64 acc3[2] = {0,0};   // sum a'*wk2 + b'*ek2

    const float4* swbase = (const float4*)sw + fg * 4;   // 16 float4 per tap

    #pragma unroll 1
    for (int kh = 0; kh < KK; kh++) {
        #pragma unroll
        for (int kw = 0; kw < KK; kw++) {
            #pragma unroll
            for (int c = 0; c < C_; c++) {
                const int tap = (kh * KK + kw) * C_ + c;
                const float4* wp4 = swbase + tap * 16;
                float4 w0 = wp4[0];
                float4 w1 = wp4[1];
                float4 w2 = wp4[2];
                float4 w3 = wp4[3];
                const u64* w0u = (const u64*)&w0;
                const u64* w1u = (const u64*)&w1;
                const u64* w2u = (const u64*)&w2;
                const u64* w3u = (const u64*)&w3;

                float4 in = sin_[c][kh][wo + kw];
                u64 ax = dup2(in.x);
                u64 bx = dup2(in.y);
                u64 az = dup2(in.z);
                u64 bw = dup2(in.w);

                #pragma unroll
                for (int j = 0; j < 2; j++) {
                    acc0[j] = ffma2(ax, w0u[j], acc0[j]);
                    acc1[j] = ffma2(ax, w1u[j], ffma2(bx, w0u[j], acc1[j]));
                    acc2[j] = ffma2(az, w2u[j], acc2[j]);
                    acc3[j] = ffma2(az, w3u[j], ffma2(bw, w2u[j], acc3[j]));
                }
            }
        }
    }

    // Epilogue: y = num1/den1 + num2/den2 + bias (denominators strictly > 0)
    float* op = out + (((size_t)n * F_ + fg * 4) * HO + ho) * WO + wo;
    #pragma unroll
    for (int j = 0; j < 2; j++) {
        float2 d1 = unpk2(acc0[j]);
        float2 n1 = unpk2(acc1[j]);
        float2 d2 = unpk2(acc2[j]);
        float2 n2 = unpk2(acc3[j]);
        int f = 2 * j;
        float y0 = __fdividef(n1.x, d1.x) + __fdividef(n2.x, d2.x) + bias[fg*4 + f];
        float y1 = __fdividef(n1.y, d1.y) + __fdividef(n2.y, d2.y) + bias[fg*4 + f + 1];
        op[(size_t)f       * HO * WO] = y0;
        op[(size_t)(f + 1) * HO * WO] = y1;
    }
}

extern "C" void kernel_launch(void* const* d_in, const int* in_sizes, int n_in,
                              void* d_out, int out_size) {
    const float* x    = (const float*)d_in[0];
    const float* k1   = (const float*)d_in[1];
    const float* k2   = (const float*)d_in[2];
    const float* bias = (const float*)d_in[3];
    float* out = (float*)d_out;

    dim3 grid(HO, N_);
    dim3 block(64, 4);
    smorph_fused_kernel<<<grid, block>>>(x, k1, k2, bias, out);
}

// round 6
// speedup vs baseline: 1.2412x; 1.0694x over previous
#include <cuda_runtime.h>

#define N_   8
#define C_   4
#define H_   64
#define W_   64
#define F_   16
#define KK   5
#define HO   60
#define WO   60
#define NTAPS (KK*KK*C_)     // 100

typedef unsigned long long u64;

__device__ __forceinline__ u64 ffma2(u64 a, u64 b, u64 c) {
    u64 d; asm("fma.rn.f32x2 %0, %1, %2, %3;" : "=l"(d) : "l"(a), "l"(b), "l"(c)); return d;
}
__device__ __forceinline__ u64 dup2(float x) {
    u64 d; asm("mov.b64 %0, {%1, %1};" : "=l"(d) : "f"(x)); return d;
}
__device__ __forceinline__ float2 unpk2(u64 v) {
    float2 r; asm("mov.b64 {%0, %1}, %2;" : "=f"(r.x), "=f"(r.y) : "l"(v)); return r;
}

// Block = one (n, ho) output row. blockDim (32,4): x = lane, y = fg.
// Each thread computes TWO pixels (wo = lane, lane+32) for 4 filters
// (2 f32x2 pairs). The broadcast weight loads per tap now serve 2 outputs,
// cutting smem wavefronts per output from ~12 to ~8.
__global__ __launch_bounds__(128) void smorph_fused_kernel(
    const float* __restrict__ x, const float* __restrict__ k1,
    const float* __restrict__ k2, const float* __restrict__ bias,
    float* __restrict__ out)
{
    // sw layout per tap (64 floats): [fg][ w0[4] w1[4] w2[4] w3[4] ]
    __shared__ __align__(16) float  sw[NTAPS * 64];   // 25600 B
    __shared__ float4 sin_[C_][KK][W_];               // 20480 B

    const int ho  = blockIdx.x;
    const int n   = blockIdx.y;
    const int tid = threadIdx.y * 32 + threadIdx.x;   // 0..127

    // ---- Phase 1: weight transform (i = tap*16 + f) ----
    #pragma unroll
    for (int i = tid; i < NTAPS * F_; i += 128) {
        int tap = i >> 4;
        int f   = i & 15;
        int fgw = f >> 2;
        int fi  = f & 3;
        float v1 = k1[i], v2 = k2[i];
        float e1 = __expf(v1), e2 = __expf(v2);
        float* p = sw + tap * 64 + fgw * 16 + fi;
        p[0]  = e1;
        p[4]  = v1 * e1;
        p[8]  = e2;
        p[12] = v2 * e2;
    }

    // ---- Phase 2: input transform for rows ho..ho+4, all channels ----
    const float* gx = x + (size_t)n * C_ * H_ * W_;
    float4* sflat = &sin_[0][0][0];
    #pragma unroll
    for (int i = tid; i < C_ * KK * W_; i += 128) {
        int w  = i & (W_ - 1);
        int r  = i >> 6;            // c*KK + dh
        int c  = r / KK;
        int dh = r - c * KK;
        float xv = gx[(c * H_ + ho + dh) * W_ + w];
        float e  = __expf(xv);
        float en = __expf(-xv);
        sflat[i] = make_float4(e, xv * e, en, -xv * en);
    }
    __syncthreads();

    const int tx  = threadIdx.x;
    const int fg  = threadIdx.y;                 // filters fg*4 .. fg*4+3
    const int wo0 = tx;
    const int wo1 = (tx + 32 < WO) ? (tx + 32) : (WO - 1);   // clamp; store masked

    // acc[t][px][pair]
    u64 acc0[2][2] = {{0,0},{0,0}};   // sum a * ek1
    u64 acc1[2][2] = {{0,0},{0,0}};   // sum a*wk1 + b*ek1
    u64 acc2[2][2] = {{0,0},{0,0}};   // sum a' * ek2
    u64 acc3[2][2] = {{0,0},{0,0}};   // sum a'*wk2 + b'*ek2

    const float4* swbase = (const float4*)sw + fg * 4;   // 16 float4 per tap

    #pragma unroll 1
    for (int kh = 0; kh < KK; kh++) {
        #pragma unroll
        for (int kw = 0; kw < KK; kw++) {
            #pragma unroll
            for (int c = 0; c < C_; c++) {
                const int tap = (kh * KK + kw) * C_ + c;
                const float4* wp4 = swbase + tap * 16;
                float4 w0 = wp4[0];
                float4 w1 = wp4[1];
                float4 w2 = wp4[2];
                float4 w3 = wp4[3];
                const u64* w0u = (const u64*)&w0;
                const u64* w1u = (const u64*)&w1;
                const u64* w2u = (const u64*)&w2;
                const u64* w3u = (const u64*)&w3;

                float4 i0 = sin_[c][kh][wo0 + kw];
                float4 i1 = sin_[c][kh][wo1 + kw];

                {   // pixel 0
                    u64 ax = dup2(i0.x), bx = dup2(i0.y);
                    u64 az = dup2(i0.z), bw = dup2(i0.w);
                    #pragma unroll
                    for (int j = 0; j < 2; j++) {
                        acc0[0][j] = ffma2(ax, w0u[j], acc0[0][j]);
                        acc1[0][j] = ffma2(ax, w1u[j], ffma2(bx, w0u[j], acc1[0][j]));
                        acc2[0][j] = ffma2(az, w2u[j], acc2[0][j]);
                        acc3[0][j] = ffma2(az, w3u[j], ffma2(bw, w2u[j], acc3[0][j]));
                    }
                }
                {   // pixel 1
                    u64 ax = dup2(i1.x), bx = dup2(i1.y);
                    u64 az = dup2(i1.z), bw = dup2(i1.w);
                    #pragma unroll
                    for (int j = 0; j < 2; j++) {
                        acc0[1][j] = ffma2(ax, w0u[j], acc0[1][j]);
                        acc1[1][j] = ffma2(ax, w1u[j], ffma2(bx, w0u[j], acc1[1][j]));
                        acc2[1][j] = ffma2(az, w2u[j], acc2[1][j]);
                        acc3[1][j] = ffma2(az, w3u[j], ffma2(bw, w2u[j], acc3[1][j]));
                    }
                }
            }
        }
    }

    // Epilogue: y = num1/den1 + num2/den2 + bias (denominators strictly > 0)
    #pragma unroll
    for (int px = 0; px < 2; px++) {
        int wo = px ? (tx + 32) : tx;
        if (wo >= WO) break;
        float* op = out + (((size_t)n * F_ + fg * 4) * HO + ho) * WO + wo;
        #pragma unroll
        for (int j = 0; j < 2; j++) {
            float2 d1 = unpk2(acc0[px][j]);
            float2 n1 = unpk2(acc1[px][j]);
            float2 d2 = unpk2(acc2[px][j]);
            float2 n2 = unpk2(acc3[px][j]);
            int f = 2 * j;
            float y0 = __fdividef(n1.x, d1.x) + __fdividef(n2.x, d2.x) + bias[fg*4 + f];
            float y1 = __fdividef(n1.y, d1.y) + __fdividef(n2.y, d2.y) + bias[fg*4 + f + 1];
            op[(size_t)f       * HO * WO] = y0;
            op[(size_t)(f + 1) * HO * WO] = y1;
        }
    }
}

extern "C" void kernel_launch(void* const* d_in, const int* in_sizes, int n_in,
                              void* d_out, int out_size) {
    const float* x    = (const float*)d_in[0];
    const float* k1   = (const float*)d_in[1];
    const float* k2   = (const float*)d_in[2];
    const float* bias = (const float*)d_in[3];
    float* out = (float*)d_out;

    dim3 grid(HO, N_);
    dim3 block(32, 4);
    smorph_fused_kernel<<<grid, block>>>(x, k1, k2, bias, out);
}